// round 17
// baseline (speedup 1.0000x reference)
#include <cuda_runtime.h>
#include <cuda_fp16.h>
#include <cstdint>

// Problem constants (fixed by the dataset)
#define NN   50000
#define EE   1600000
#define EN   1650000      // EE + NN self loops
#define IND  256
#define HID  256
#define OUTD 48
#define KHOP 10
#define NBS  196          // ceil(NN/256) scan blocks

typedef unsigned long long u64;

// Packed fp32x2 FMA: d = a*b + d (elementwise on 2 packed floats)
#define FMA2(acc, a, b) \
    asm("fma.rn.f32x2 %0, %1, %2, %0;" : "+l"(acc) : "l"(a), "l"(b))
#define PACK_DUP(out, f) do { \
    unsigned _u = __float_as_uint(f); \
    asm("mov.b64 %0, {%1, %1};" : "=l"(out) : "r"(_u)); \
} while (0)
#define UNPACK2(lo, hi, in) \
    asm("mov.b64 {%0, %1}, %2;" : "=r"(lo), "=r"(hi) : "l"(in))

// ---------------- scratch (device globals; no allocation allowed) ----------
__device__ float     g_relu[NN * HID];    // relu(x@W1+b1)
__device__ float     g_h[NN * OUTD];      // MLP output h (fp32)
__device__ uint2     g_rf0[NN * 12];      // fp16 r ping (48 halves per node)
__device__ uint2     g_rf1[NN * 12];      // fp16 r pong
__device__ int       g_deg[NN];
__device__ int       g_scan[NN];
__device__ int       g_bsum[256];
__device__ int       g_rowptr[NN + 1];
__device__ int       g_cursor[NN];
__device__ float     g_dinv[NN];
__device__ long long g_edges[EN];         // packed {src:int32 (lo), norm:f32 (hi)}

// ---------------- CSR build -------------------------------------------------
__global__ void k_init_deg() {
    int i = blockIdx.x * blockDim.x + threadIdx.x;
    if (i < NN) g_deg[i] = 1;   // self loop
}

__global__ void k_count(const int* __restrict__ ei) {
    int i = blockIdx.x * blockDim.x + threadIdx.x;
    if (i < EE) {
        int d = ei[EE + i];
        if ((unsigned)d < NN) atomicAdd(&g_deg[d], 1);
    }
}

__global__ void k_scan1() {
    __shared__ int s[256];
    int tx = threadIdx.x;
    int i = blockIdx.x * 256 + tx;
    int v = (i < NN) ? g_deg[i] : 0;
    s[tx] = v;
    __syncthreads();
    #pragma unroll
    for (int off = 1; off < 256; off <<= 1) {
        int add = (tx >= off) ? s[tx - off] : 0;
        __syncthreads();
        s[tx] += add;
        __syncthreads();
    }
    if (i < NN) g_scan[i] = s[tx];
    if (tx == 255) g_bsum[blockIdx.x] = s[255];
}

// scan of block sums fused in: each block redundantly scans g_bsum in smem
// and extracts its own exclusive offset.
__global__ void k_scan3() {
    __shared__ int s[256];
    int tx = threadIdx.x;
    int b  = blockIdx.x;
    int bv = (tx < NBS) ? g_bsum[tx] : 0;
    s[tx] = bv;
    __syncthreads();
    #pragma unroll
    for (int off = 1; off < 256; off <<= 1) {
        int add = (tx >= off) ? s[tx - off] : 0;
        __syncthreads();
        s[tx] += add;
        __syncthreads();
    }
    int boff = s[b] - g_bsum[b];   // exclusive offset of this block's chunk
    int i = b * 256 + tx;
    if (i >= NN) return;
    int incl = g_scan[i] + boff;
    g_rowptr[i + 1] = incl;
    g_cursor[i] = incl - g_deg[i];           // exclusive start
    g_dinv[i] = rsqrtf((float)g_deg[i]);     // deg >= 1 always
    if (i == 0) g_rowptr[0] = 0;
}

__global__ void k_fill(const int* __restrict__ ei) {
    int i = blockIdx.x * blockDim.x + threadIdx.x;
    if (i >= EN) return;
    int s, d;
    if (i < EE) { s = ei[i]; d = ei[EE + i]; }
    else        { s = i - EE; d = s; }
    if ((unsigned)s >= NN || (unsigned)d >= NN) return;
    float w = g_dinv[s] * g_dinv[d];
    int pos = atomicAdd(&g_cursor[d], 1);
    g_edges[pos] = (long long)(unsigned)s |
                   ((long long)__float_as_uint(w) << 32);
}

// ---------------- GEMM1: g_relu = relu(x @ W1 + b1) -------------------------
// 128x64 tile, 256 threads, 8 rows x 4 cols per thread, packed f32x2 FMAs.
// Smaller per-thread state (16 u64 accs) -> 3 CTAs/SM (24 warps) for
// latency hiding; fma pipe stays the binding resource.
#define KC 16
__global__ void __launch_bounds__(256, 3)
k_gemm1(const float* __restrict__ A, const float* __restrict__ B,
        const float* __restrict__ bias) {
    __shared__ __align__(16) float As[KC][132];   // transposed A tile (k-major)
    __shared__ __align__(16) float Bs[KC][68];    // 64 cols + pad
    int tid  = threadIdx.x;
    int brow = blockIdx.y * 128;
    int bcol = blockIdx.x * 64;
    int tr = tid >> 4, tc = tid & 15;

    // A load: row = tid>>1, k-offset = (tid&1)*8 (two float4)
    int arow = tid >> 1;
    int ak   = (tid & 1) << 3;
    int grow = brow + arow;
    bool aok = grow < NN;
    const float* aptr = A + (size_t)grow * IND + ak;
    // B load: k-row = tid>>4 (0..15), col-offset = (tid&15)*4 (one float4)
    int bk = tid >> 4;
    int bc = (tid & 15) << 2;
    const float* bptr = B + bk * HID + bcol + bc;

    float4 pa0, pa1, pb0;
    const float4 z4 = make_float4(0.f, 0.f, 0.f, 0.f);
    pa0 = aok ? *(const float4*)(aptr)     : z4;
    pa1 = aok ? *(const float4*)(aptr + 4) : z4;
    pb0 = *(const float4*)(bptr);

    u64 acc2[8][2];   // 8 rows x 2 col-pairs (4 cols)
    #pragma unroll
    for (int i = 0; i < 8; ++i) {
        acc2[i][0] = 0ull;
        acc2[i][1] = 0ull;
    }

    #pragma unroll 1
    for (int c = 0; c < IND / KC; ++c) {
        __syncthreads();
        As[ak + 0][arow] = pa0.x;
        As[ak + 1][arow] = pa0.y;
        As[ak + 2][arow] = pa0.z;
        As[ak + 3][arow] = pa0.w;
        As[ak + 4][arow] = pa1.x;
        As[ak + 5][arow] = pa1.y;
        As[ak + 6][arow] = pa1.z;
        As[ak + 7][arow] = pa1.w;
        *(float4*)&Bs[bk][bc] = pb0;
        __syncthreads();
        if (c + 1 < IND / KC) {
            const float* ap = aptr + (c + 1) * KC;
            pa0 = aok ? *(const float4*)(ap)     : z4;
            pa1 = aok ? *(const float4*)(ap + 4) : z4;
            pb0 = *(const float4*)(bptr + (c + 1) * KC * HID);
        }
        #pragma unroll
        for (int k = 0; k < KC; ++k) {
            float4 a0 = *(const float4*)&As[k][tr << 2];
            float4 a1 = *(const float4*)&As[k][64 + (tr << 2)];
            ulonglong2 bq = *(const ulonglong2*)&Bs[k][tc << 2];
            float av[8] = {a0.x, a0.y, a0.z, a0.w, a1.x, a1.y, a1.z, a1.w};
            #pragma unroll
            for (int i = 0; i < 8; ++i) {
                u64 aa;
                PACK_DUP(aa, av[i]);
                FMA2(acc2[i][0], aa, bq.x);
                FMA2(acc2[i][1], aa, bq.y);
            }
        }
    }

    float4 bb = *(const float4*)(bias + bcol + (tc << 2));
    float bsv[4] = {bb.x, bb.y, bb.z, bb.w};
    #pragma unroll
    for (int half = 0; half < 2; ++half) {
        #pragma unroll
        for (int i = 0; i < 4; ++i) {
            int ii = half * 4 + i;
            int gr = brow + half * 64 + (tr << 2) + i;
            if (gr < NN) {
                unsigned lo, hi;
                float v[4];
                UNPACK2(lo, hi, acc2[ii][0]);
                v[0] = __uint_as_float(lo);
                v[1] = __uint_as_float(hi);
                UNPACK2(lo, hi, acc2[ii][1]);
                v[2] = __uint_as_float(lo);
                v[3] = __uint_as_float(hi);
                float4 o;
                o.x = fmaxf(v[0] + bsv[0], 0.f);
                o.y = fmaxf(v[1] + bsv[1], 0.f);
                o.z = fmaxf(v[2] + bsv[2], 0.f);
                o.w = fmaxf(v[3] + bsv[3], 0.f);
                *(float4*)(g_relu + (size_t)gr * HID + bcol + (tc << 2)) = o;
            }
        }
    }
}

// ---------------- GEMM2: g_h = g_relu @ W2 + b2; seed r_K = temp[K]*h -------
// 128-row tile (grid 391 -> 2.6 waves), 256 threads, 4 rows x 6 cols/thread.
#define G2KC 32
__global__ void __launch_bounds__(256)
k_gemm2(const float* __restrict__ W, const float* __restrict__ bias,
        const float* __restrict__ temp) {
    __shared__ __align__(16) float Ws[G2KC * 48];     // 6 KB
    __shared__ __align__(16) float As[G2KC][132];     // k-major, pad 132
    int tid  = threadIdx.x;
    int row0 = blockIdx.x * 128;
    int rg = tid >> 3;    // 0..31 -> rows rg*4..rg*4+3
    int cg = tid & 7;     // cols cg*6..cg*6+5

    u64 acc2[4][3];
    #pragma unroll
    for (int i = 0; i < 4; ++i)
        #pragma unroll
        for (int j = 0; j < 3; ++j) acc2[i][j] = 0ull;

    for (int kb = 0; kb < HID; kb += G2KC) {
        __syncthreads();
        #pragma unroll
        for (int j = 0; j < 6; ++j) {
            int li = tid + j * 256;       // < 1536
            Ws[li] = W[kb * 48 + li];
        }
        #pragma unroll
        for (int j = 0; j < 4; ++j) {
            int f = tid + j * 256;        // < 1024 float4 loads
            int row = f >> 3;
            int q = f & 7;
            int gr = row0 + row;
            float4 v = (gr < NN) ? *(const float4*)(g_relu + (size_t)gr * HID + kb + q * 4)
                                 : make_float4(0.f, 0.f, 0.f, 0.f);
            As[q * 4 + 0][row] = v.x;
            As[q * 4 + 1][row] = v.y;
            As[q * 4 + 2][row] = v.z;
            As[q * 4 + 3][row] = v.w;
        }
        __syncthreads();
        #pragma unroll 4
        for (int k = 0; k < G2KC; ++k) {
            const float* wrow = Ws + k * 48 + cg * 6;
            u64 wp0 = *(const u64*)(wrow);
            u64 wp1 = *(const u64*)(wrow + 2);
            u64 wp2 = *(const u64*)(wrow + 4);
            float4 a0 = *(const float4*)&As[k][rg << 2];
            float av[4] = {a0.x, a0.y, a0.z, a0.w};
            #pragma unroll
            for (int i = 0; i < 4; ++i) {
                u64 aa;
                PACK_DUP(aa, av[i]);
                FMA2(acc2[i][0], aa, wp0);
                FMA2(acc2[i][1], aa, wp1);
                FMA2(acc2[i][2], aa, wp2);
            }
        }
    }

    float tK = __ldg(temp + KHOP);     // (1-alpha)^K
    __half* rf = (__half*)g_rf0;
    float bs[6];
    #pragma unroll
    for (int j = 0; j < 6; ++j) bs[j] = bias[cg * 6 + j];
    #pragma unroll
    for (int i = 0; i < 4; ++i) {
        int gr = row0 + rg * 4 + i;
        if (gr < NN) {
            unsigned lo, hi;
            #pragma unroll
            for (int j = 0; j < 3; ++j) {
                UNPACK2(lo, hi, acc2[i][j]);
                float v0 = __uint_as_float(lo) + bs[2 * j];
                float v1 = __uint_as_float(hi) + bs[2 * j + 1];
                int c = cg * 6 + 2 * j;
                g_h[(size_t)gr * 48 + c]     = v0;
                g_h[(size_t)gr * 48 + c + 1] = v1;
                rf[(size_t)gr * 48 + c]     = __float2half_rn(tK * v0);
                rf[(size_t)gr * 48 + c + 1] = __float2half_rn(tK * v1);
            }
        }
    }
}

// ---------------- propagation (Horner): r_k = temp[k]*h + H r_{k+1} ---------
// 12 threads per node, 16 nodes per 192-thread block, smem-staged edges.
#define ECAP 768
__global__ void __launch_bounds__(192)
k_prop(const float* __restrict__ temp, int k, int srcbuf,
       float* __restrict__ out) {
    __shared__ __align__(16) int2 se[ECAP];
    int tid  = threadIdx.x;
    int n0   = blockIdx.x * 16;
    int node = n0 + tid / 12;
    int fx   = tid - (tid / 12) * 12;
    int ln   = tid / 12;          // node slot within block (0..15)

    const uint2* __restrict__ cur = srcbuf ? g_rf1 : g_rf0;
    uint2*       __restrict__ nxt = srcbuf ? g_rf0 : g_rf1;
    const int2* __restrict__ ed = (const int2*)g_edges;

    int base  = g_rowptr[n0];
    int tot   = g_rowptr[n0 + 16] - base;
    int staged = tot < ECAP ? tot : ECAP;

    // Cooperative coalesced stage of this block's edge records
    for (int i = tid; i < staged; i += 192) se[i] = ed[base + i];

    int beg = g_rowptr[node] - base;
    int end = g_rowptr[node + 1] - base;
    __syncthreads();

    float4 acc = make_float4(0.f, 0.f, 0.f, 0.f);
    int mid = end < staged ? end : staged;
    #pragma unroll 4
    for (int p = beg; p < mid; ++p) {
        int2 e = se[p];
        float w = __int_as_float(e.y);
        uint2 v = __ldg(&cur[e.x * 12 + fx]);
        __half2 h0 = *reinterpret_cast<__half2*>(&v.x);
        __half2 h1 = *reinterpret_cast<__half2*>(&v.y);
        float2 f0 = __half22float2(h0);
        float2 f1 = __half22float2(h1);
        acc.x = fmaf(w, f0.x, acc.x);
        acc.y = fmaf(w, f0.y, acc.y);
        acc.z = fmaf(w, f1.x, acc.z);
        acc.w = fmaf(w, f1.y, acc.w);
    }
    // Residual (only if block edge count exceeded ECAP)
    for (int p = (beg > staged ? beg : staged); p < end; ++p) {
        int2 e = ed[base + p];
        float w = __int_as_float(e.y);
        uint2 v = __ldg(&cur[e.x * 12 + fx]);
        __half2 h0 = *reinterpret_cast<__half2*>(&v.x);
        __half2 h1 = *reinterpret_cast<__half2*>(&v.y);
        float2 f0 = __half22float2(h0);
        float2 f1 = __half22float2(h1);
        acc.x = fmaf(w, f0.x, acc.x);
        acc.y = fmaf(w, f0.y, acc.y);
        acc.z = fmaf(w, f1.x, acc.z);
        acc.w = fmaf(w, f1.y, acc.w);
    }

    float g = __ldg(temp + k);
    float4 hv = *(const float4*)(g_h + (size_t)node * 48 + fx * 4);
    float4 r;
    r.x = fmaf(g, hv.x, acc.x);
    r.y = fmaf(g, hv.y, acc.y);
    r.z = fmaf(g, hv.z, acc.z);
    r.w = fmaf(g, hv.w, acc.w);

    if (k != 0) {
        __half2 o0 = __floats2half2_rn(r.x, r.y);
        __half2 o1 = __floats2half2_rn(r.z, r.w);
        uint2 o;
        o.x = *reinterpret_cast<unsigned*>(&o0);
        o.y = *reinterpret_cast<unsigned*>(&o1);
        nxt[node * 12 + fx] = o;
        return;
    }

    // ---- k == 0: fused log-softmax over the node's 48 values ----
    __shared__ float pm[16][12];
    __shared__ float ps[16][12];
    __shared__ float red[16];
    float lmax = fmaxf(fmaxf(r.x, r.y), fmaxf(r.z, r.w));
    pm[ln][fx] = lmax;
    __syncthreads();
    if (fx == 0) {
        float m = pm[ln][0];
        #pragma unroll
        for (int j = 1; j < 12; ++j) m = fmaxf(m, pm[ln][j]);
        red[ln] = m;
    }
    __syncthreads();
    float m = red[ln];
    float es = expf(r.x - m) + expf(r.y - m) + expf(r.z - m) + expf(r.w - m);
    ps[ln][fx] = es;
    __syncthreads();
    if (fx == 0) {
        float ssum = 0.f;
        #pragma unroll
        for (int j = 0; j < 12; ++j) ssum += ps[ln][j];
        red[ln] = m + logf(ssum);
    }
    __syncthreads();
    float lse = red[ln];
    float4 o;
    o.x = r.x - lse;
    o.y = r.y - lse;
    o.z = r.z - lse;
    o.w = r.w - lse;
    *(float4*)(out + (size_t)node * 48 + fx * 4) = o;
}

// ---------------- launch ----------------------------------------------------
extern "C" void kernel_launch(void* const* d_in, const int* in_sizes, int n_in,
                              void* d_out, int out_size) {
    const float* x    = (const float*)d_in[0];
    const int*   ei   = (const int*)d_in[1];      // int32 [2, EE]
    const float* W1   = (const float*)d_in[2];
    const float* b1   = (const float*)d_in[3];
    const float* W2   = (const float*)d_in[4];
    const float* b2   = (const float*)d_in[5];
    const float* temp = (const float*)d_in[6];
    float* out = (float*)d_out;
    (void)in_sizes; (void)n_in; (void)out_size;

    // Lazily-created side stream + fork/join events (host handles only; no
    // device memory). Behavior is identical on every call.
    static cudaStream_t s2 = nullptr;
    static cudaEvent_t evFork = nullptr, evJoin = nullptr;
    if (s2 == nullptr) {
        cudaStreamCreateWithFlags(&s2, cudaStreamNonBlocking);
        cudaEventCreateWithFlags(&evFork, cudaEventDisableTiming);
        cudaEventCreateWithFlags(&evJoin, cudaEventDisableTiming);
    }

    // Fork: CSR build (independent of MLP) runs on s2, MLP on the capture
    // stream. Join before propagation (needs both).
    cudaEventRecord(evFork, 0);
    cudaStreamWaitEvent(s2, evFork, 0);

    // CSR branch on s2
    k_init_deg<<<(NN + 255) / 256, 256, 0, s2>>>();
    k_count<<<(EE + 255) / 256, 256, 0, s2>>>(ei);
    k_scan1<<<NBS, 256, 0, s2>>>();
    k_scan3<<<NBS, 256, 0, s2>>>();
    k_fill<<<(EE + NN + 255) / 256, 256, 0, s2>>>(ei);
    cudaEventRecord(evJoin, s2);

    // MLP branch on the main (capture) stream
    dim3 g1(4, (NN + 127) / 128);
    k_gemm1<<<g1, 256>>>(x, W1, b1);
    k_gemm2<<<(NN + 127) / 128, 256>>>(W2, b2, temp);

    // Join
    cudaStreamWaitEvent(0, evJoin, 0);

    // Horner propagation: r_k = temp[k]*h + H r_{k+1}, k = K-1 .. 0
    // (k = 0 writes log-softmaxed output directly)
    for (int k = KHOP - 1; k >= 0; --k) {
        int s = KHOP - k;                       // step number 1..K
        int srcbuf = (s & 1) ? 0 : 1;           // r_{k+1} location
        k_prop<<<(NN * 12) / 192, 192>>>(temp, k, srcbuf, out);
    }
}